// round 11
// baseline (speedup 1.0000x reference)
#include <cuda_runtime.h>
#include <cstdint>

// Problem constants
#define BB 8
#define SS 2048
#define DD 768
#define HH 768
#define MT (BB*SS)        // 16384

typedef long long ll;

// ---------------------------------------------------------------------------
// Packed operand layout (per row, K = logical reduction length), int8 pieces:
//   value ≈ (i1*256 + i2) * Δ   (Δ = R/32768, range ±R, all powers of 2)
//   A-side row (4K bytes): [ i1 | i1 | i2 | i2 ]
//   B-side row (4K bytes): [ j1 | j2 | j1 | j2 ]
// K-ranges give products i1j1, i1j2, i2j1, i2j2; s32 accum flushed to fp32
// with scales 65536*S, 256*S (two ranges), S, where S = Δa*Δb.
// ---------------------------------------------------------------------------
__device__ __align__(16) uint8_t g_xp[(ll)MT * 4 * DD];
__device__ __align__(16) uint8_t g_yp[(ll)MT * 4 * DD];
__device__ __align__(16) uint8_t g_wp[3][(ll)HH * 4 * DD];
__device__ __align__(16) float   g_q [(ll)MT * HH];
__device__ __align__(16) float   g_v [(ll)MT * HH];           // V' = q ⊙ (yWv+bv)
__device__ __align__(16) uint8_t g_qp[(ll)MT * 4 * HH];       // A-side, R=4
__device__ __align__(16) uint8_t g_kp[(ll)MT * 4 * HH];       // B-side, R=4
__device__ __align__(16) float   g_s [(ll)BB * SS * SS];      // scores
__device__ __align__(16) uint8_t g_pp[(ll)MT * 4 * SS];       // probs, A-side, R=2
__device__ __align__(16) uint8_t g_vtp[(ll)BB * HH * 4 * SS]; // V'^T, B-side, R=8

// ---------------------------------------------------------------------------
// helpers
// ---------------------------------------------------------------------------
__device__ __forceinline__ uint32_t s2u(const void* p) {
    return (uint32_t)__cvta_generic_to_shared(p);
}
__device__ __forceinline__ int q8i(float v, float s) {
    int i = __float2int_rn(v * s);
    return min(127, max(-128, i));
}
__device__ __forceinline__ void ldmx4(uint32_t* r, uint32_t a) {
    asm volatile("ldmatrix.sync.aligned.m8n8.x4.shared.b16 {%0,%1,%2,%3}, [%4];"
                 : "=r"(r[0]), "=r"(r[1]), "=r"(r[2]), "=r"(r[3]) : "r"(a));
}
__device__ __forceinline__ void mmas8(int* c, const uint32_t* a, const uint32_t* b) {
    asm volatile("mma.sync.aligned.m16n8k32.row.col.s32.s8.s8.s32 "
                 "{%0,%1,%2,%3}, {%4,%5,%6,%7}, {%8,%9}, {%0,%1,%2,%3};"
                 : "+r"(c[0]), "+r"(c[1]), "+r"(c[2]), "+r"(c[3])
                 : "r"(a[0]), "r"(a[1]), "r"(a[2]), "r"(a[3]), "r"(b[0]), "r"(b[1]));
}
__device__ __forceinline__ void cp16(uint32_t dst, const void* src) {
    asm volatile("cp.async.cg.shared.global [%0], [%1], 16;"
                 :: "r"(dst), "l"(src) : "memory");
}
__device__ __forceinline__ void cp_commit() {
    asm volatile("cp.async.commit_group;" ::: "memory");
}

// ---------------------------------------------------------------------------
// INT8 16-bit split NT GEMM. Block tile 128x128, 8 warps (2x4), warp 64x32.
// Tile = 64 bytes/row (2 x k32 mma). smem row = 80B (conflict-free ldmatrix).
// 6-stage cp.async ring, occupancy 1.
// ---------------------------------------------------------------------------
#define ROWB 80
#define MAT_BYTES (128 * ROWB)         // 10240
#define STG_BYTES (2 * MAT_BYTES)      // 20480
#define NSTAGE 6
#define GEMM_SMEM (NSTAGE * STG_BYTES) // 122880

__device__ __forceinline__ void issue_stage(const uint8_t* Ag, const uint8_t* Bg,
                                            ll rowB, int t, uint32_t sA,
                                            int lr, int lcB)
{
    const ll off = (ll)t * 64 + lcB;
    const uint32_t sB = sA + MAT_BYTES;
    cp16(sA + lr * ROWB + lcB,        Ag + (ll)lr * rowB + off);
    cp16(sA + (lr + 64) * ROWB + lcB, Ag + (ll)(lr + 64) * rowB + off);
    cp16(sB + lr * ROWB + lcB,        Bg + (ll)lr * rowB + off);
    cp16(sB + (lr + 64) * ROWB + lcB, Bg + (ll)(lr + 64) * rowB + off);
    cp_commit();
}

__global__ __launch_bounds__(256, 1)
void gemm_i8(const uint8_t* __restrict__ A, ll sAz,
             const uint8_t* __restrict__ B, ll sBz,
             float* __restrict__ Cf, uint8_t* __restrict__ Cpack, ll sCz,
             const float* __restrict__ bias,
             const float* __restrict__ mul,
             int N, int Kf, int side,            // side: 0 none, 1 A-pack, 2 B-pack
             float S,                            // Δa*Δb
             float pInv1, float pStep, float pInv2)  // pack consts (128/R, R/128, 32768/R)
{
    extern __shared__ char dyn[];
    const uint32_t sbase = s2u(dyn);

    const int tid = threadIdx.x;
    const int bx = blockIdx.x, by = blockIdx.y, z = blockIdx.z;
    const int lane = tid & 31, wid = tid >> 5;
    const int wm = (wid >> 2) * 64;
    const int wn = (wid & 3) * 32;

    const ll rowB = 4LL * Kf;
    const uint8_t* Ag = A + (ll)z * sAz + (ll)by * 128 * rowB;
    const uint8_t* Bg = B + (ll)z * sBz + (ll)bx * 128 * rowB;

    const int lr  = tid >> 2;
    const int lcB = (tid & 3) * 16;

    int   acc [4][4][4];
    float accf[4][4][4];
    #pragma unroll
    for (int i = 0; i < 4; i++)
        #pragma unroll
        for (int j = 0; j < 4; j++)
            #pragma unroll
            for (int q = 0; q < 4; q++) { acc[i][j][q] = 0; accf[i][j][q] = 0.0f; }

#define FLUSH(sc) do {                                                          \
    _Pragma("unroll") for (int i = 0; i < 4; i++)                               \
    _Pragma("unroll") for (int j = 0; j < 4; j++)                               \
    _Pragma("unroll") for (int q = 0; q < 4; q++) {                             \
        accf[i][j][q] = fmaf((sc), (float)acc[i][j][q], accf[i][j][q]);         \
        acc[i][j][q] = 0;                                                       \
    }                                                                           \
} while (0)

    // fragment smem BYTE offsets (per lane) — layout identical to fp8 round (passed)
    const int aoff = (wm + (lane & 15)) * ROWB + (lane >> 4) * 16;
    const int bg4 = lane >> 3;
    const int boff = (wn + ((bg4 >> 1) * 8) + (lane & 7)) * ROWB + (bg4 & 1) * 16;

    const int T = Kf / 64;          // tiles per product-range
    const int ntile = 4 * T;

    #pragma unroll
    for (int s = 0; s < 5; s++)
        issue_stage(Ag, Bg, rowB, s, sbase + s * STG_BYTES, lr, lcB);

    const float s1 = S * 65536.0f, s2 = S * 256.0f;

    for (int kt = 0; kt < ntile; kt++) {
        asm volatile("cp.async.wait_group %0;" :: "n"(4) : "memory");
        __syncthreads();
        if (kt + 5 < ntile)
            issue_stage(Ag, Bg, rowB, kt + 5,
                        sbase + ((kt + 5) % NSTAGE) * STG_BYTES, lr, lcB);

        if (kt == T)          FLUSH(s1);   // i1j1 done
        else if (kt == 3 * T) FLUSH(s2);   // i1j2 + i2j1 done

        const uint32_t abase = sbase + (kt % NSTAGE) * STG_BYTES;
        const uint32_t bbase = abase + MAT_BYTES;
        #pragma unroll
        for (int ks = 0; ks < 2; ks++) {
            uint32_t af[4][4], bfr[2][4];
            #pragma unroll
            for (int mi = 0; mi < 4; mi++)
                ldmx4(af[mi], abase + aoff + mi * 16 * ROWB + ks * 32);
            #pragma unroll
            for (int bj = 0; bj < 2; bj++)
                ldmx4(bfr[bj], bbase + boff + bj * 16 * ROWB + ks * 32);
            #pragma unroll
            for (int mi = 0; mi < 4; mi++)
                #pragma unroll
                for (int ni = 0; ni < 4; ni++)
                    mmas8(acc[mi][ni], af[mi], &bfr[ni >> 1][(ni & 1) * 2]);
        }
    }
    FLUSH(S);                              // i2j2
#undef FLUSH

    // --- epilogue ---
    const int gq = lane >> 2, tig = lane & 3;
    float* Cz = Cf ? (Cf + (ll)z * sCz) : nullptr;
    const float* Mz = mul ? (mul + (ll)z * sCz) : nullptr;

    #pragma unroll
    for (int mi = 0; mi < 4; mi++) {
        #pragma unroll
        for (int ni = 0; ni < 4; ni++) {
            const int row = by * 128 + wm + mi * 16 + gq;
            const int col = bx * 128 + wn + ni * 8 + tig * 2;
            float v0 = accf[mi][ni][0], v1 = accf[mi][ni][1];
            float v2 = accf[mi][ni][2], v3 = accf[mi][ni][3];
            if (bias) {
                float b0 = bias[col], b1 = bias[col + 1];
                v0 += b0; v1 += b1; v2 += b0; v3 += b1;
            }
            const ll o0 = (ll)row * N + col;
            const ll o1 = o0 + 8LL * N;
            if (Mz) {
                v0 *= Mz[o0]; v1 *= Mz[o0 + 1];
                v2 *= Mz[o1]; v3 *= Mz[o1 + 1];
            }
            if (Cz) {
                float2 r01; r01.x = v0; r01.y = v1;
                float2 r23; r23.x = v2; r23.y = v3;
                *reinterpret_cast<float2*>(Cz + o0) = r01;
                *reinterpret_cast<float2*>(Cz + o1) = r23;
            }
            if (side) {
                uint8_t* P0 = Cpack + (ll)row * (4LL * N);
                uint8_t* P1 = Cpack + (ll)(row + 8) * (4LL * N);
                int a0 = q8i(v0, pInv1), a1 = q8i(v1, pInv1);
                int a2 = q8i(v2, pInv1), a3 = q8i(v3, pInv1);
                int b0 = q8i(fmaf((float)a0, -pStep, v0), pInv2);
                int b1 = q8i(fmaf((float)a1, -pStep, v1), pInv2);
                int b2 = q8i(fmaf((float)a2, -pStep, v2), pInv2);
                int b3 = q8i(fmaf((float)a3, -pStep, v3), pInv2);
                uchar2 hA; hA.x = (uint8_t)a0; hA.y = (uint8_t)a1;
                uchar2 hB; hB.x = (uint8_t)a2; hB.y = (uint8_t)a3;
                uchar2 lA; lA.x = (uint8_t)b0; lA.y = (uint8_t)b1;
                uchar2 lB; lB.x = (uint8_t)b2; lB.y = (uint8_t)b3;
                // A-side: i1@{0,N}, i2@{2N,3N};  B-side: i1@{0,2N}, i2@{N,3N}
                const ll offH = (side == 1) ? (ll)N : 2LL * N;
                const ll offL = (side == 1) ? 2LL * N : (ll)N;
                *reinterpret_cast<uchar2*>(P0 + col) = hA;
                *reinterpret_cast<uchar2*>(P1 + col) = hB;
                *reinterpret_cast<uchar2*>(P0 + offH + col) = hA;
                *reinterpret_cast<uchar2*>(P1 + offH + col) = hB;
                *reinterpret_cast<uchar2*>(P0 + offL + col) = lA;
                *reinterpret_cast<uchar2*>(P1 + offL + col) = lB;
                *reinterpret_cast<uchar2*>(P0 + 3LL * N + col) = lA;
                *reinterpret_cast<uchar2*>(P1 + 3LL * N + col) = lB;
            }
        }
    }
}

// ---------------------------------------------------------------------------
// fp32 -> packed A-side int split for x AND y in one launch (z selects).
// ---------------------------------------------------------------------------
__global__ void packA2(const float* __restrict__ x, const float* __restrict__ y,
                       uint8_t* __restrict__ dx, uint8_t* __restrict__ dy, int C)
{
    const int z = blockIdx.z;
    const ll r = blockIdx.y;
    const int c = blockIdx.x * 256 + threadIdx.x;
    const float* s = z ? y : x;
    uint8_t* d = (z ? dy : dx) + r * (4LL * C);
    float a = s[r * C + c];
    int i1 = q8i(a, 16.0f);                                  // R=8: 128/R
    int i2 = q8i(fmaf((float)i1, -0.0625f, a), 4096.0f);     // R/128, 32768/R
    d[c] = (uint8_t)i1;
    d[C + c] = (uint8_t)i1;
    d[2LL * C + c] = (uint8_t)i2;
    d[3LL * C + c] = (uint8_t)i2;
}

// ---------------------------------------------------------------------------
// Transposed packed B-side int split: src [P,Q] fp32 -> dst [Q rows, 4P bytes]
// ---------------------------------------------------------------------------
__global__ void packBT(const float* __restrict__ src, uint8_t* __restrict__ dst,
                       int P, int Q, ll sz, ll dz,
                       float pInv1, float pStep, float pInv2)
{
    __shared__ float t[32][33];
    const int z = blockIdx.z;
    const float* s = src + (ll)z * sz;
    uint8_t* d = dst + (ll)z * dz;
    const int c0 = blockIdx.x * 32, r0 = blockIdx.y * 32;
    const int tx = threadIdx.x, ty = threadIdx.y;

    #pragma unroll
    for (int i = 0; i < 4; i++)
        t[ty + 8 * i][tx] = s[(ll)(r0 + ty + 8 * i) * Q + c0 + tx];
    __syncthreads();
    #pragma unroll
    for (int i = 0; i < 4; i++) {
        float a = t[tx][ty + 8 * i];
        int i1 = q8i(a, pInv1);
        int i2 = q8i(fmaf((float)i1, -pStep, a), pInv2);
        uint8_t* dr = d + (ll)(c0 + ty + 8 * i) * (4LL * P);
        dr[r0 + tx] = (uint8_t)i1;            // j1
        dr[P + r0 + tx] = (uint8_t)i2;        // j2
        dr[2LL * P + r0 + tx] = (uint8_t)i1;  // j1
        dr[3LL * P + r0 + tx] = (uint8_t)i2;  // j2
    }
}

// ---------------------------------------------------------------------------
// Fused softmax + packed A-side int split (R=2): row fp32 -> g_pp row (4*SS B)
// ---------------------------------------------------------------------------
__global__ void softmax_pack(const float* __restrict__ S, uint8_t* __restrict__ P)
{
    const ll row = blockIdx.x;
    const float* p = S + row * (ll)SS;
    uint8_t* d = P + row * (4LL * SS);
    const int t = threadIdx.x;
    __shared__ float red[32];

    float v[8];
    float m = -1e30f;
    #pragma unroll
    for (int i = 0; i < 8; i++) {
        v[i] = p[t + i * 256];
        m = fmaxf(m, v[i]);
    }
    #pragma unroll
    for (int o = 16; o > 0; o >>= 1) m = fmaxf(m, __shfl_xor_sync(0xffffffffu, m, o));
    if ((t & 31) == 0) red[t >> 5] = m;
    __syncthreads();
    if (t < 32) {
        float mm = (t < 8) ? red[t] : -1e30f;
        #pragma unroll
        for (int o = 16; o > 0; o >>= 1) mm = fmaxf(mm, __shfl_xor_sync(0xffffffffu, mm, o));
        if (t == 0) red[0] = mm;
    }
    __syncthreads();
    m = red[0];
    __syncthreads();

    float sum = 0.0f;
    #pragma unroll
    for (int i = 0; i < 8; i++) {
        v[i] = __expf(v[i] - m);
        sum += v[i];
    }
    #pragma unroll
    for (int o = 16; o > 0; o >>= 1) sum += __shfl_xor_sync(0xffffffffu, sum, o);
    if ((t & 31) == 0) red[t >> 5] = sum;
    __syncthreads();
    if (t < 32) {
        float ss = (t < 8) ? red[t] : 0.0f;
        #pragma unroll
        for (int o = 16; o > 0; o >>= 1) ss += __shfl_xor_sync(0xffffffffu, ss, o);
        if (t == 0) red[0] = ss;
    }
    __syncthreads();
    const float inv = 1.0f / red[0];

    #pragma unroll
    for (int i = 0; i < 8; i++) {
        const int c = t + i * 256;
        float pr = v[i] * inv;
        int i1 = q8i(pr, 64.0f);                                    // R=2
        int i2 = q8i(fmaf((float)i1, -0.015625f, pr), 16384.0f);
        d[c] = (uint8_t)i1;
        d[SS + c] = (uint8_t)i1;
        d[2LL * SS + c] = (uint8_t)i2;
        d[3LL * SS + c] = (uint8_t)i2;
    }
}

// ---------------------------------------------------------------------------
extern "C" void kernel_launch(void* const* d_in, const int* in_sizes, int n_in,
                              void* d_out, int out_size)
{
    const float* x  = (const float*)d_in[0];
    const float* y  = (const float*)d_in[1];
    const float* Wq = (const float*)d_in[2];
    const float* bq = (const float*)d_in[3];
    const float* Wk = (const float*)d_in[4];
    const float* bk = (const float*)d_in[5];
    const float* Wv = (const float*)d_in[6];
    const float* bv = (const float*)d_in[7];
    float* out = (float*)d_out;

    uint8_t *pxp, *pyp, *pwp, *pqp, *pkp, *ppp, *pvtp;
    float *pq, *pv, *ps;
    cudaGetSymbolAddress((void**)&pxp,  g_xp);
    cudaGetSymbolAddress((void**)&pyp,  g_yp);
    cudaGetSymbolAddress((void**)&pwp,  g_wp);
    cudaGetSymbolAddress((void**)&pq,   g_q);
    cudaGetSymbolAddress((void**)&pv,   g_v);
    cudaGetSymbolAddress((void**)&pqp,  g_qp);
    cudaGetSymbolAddress((void**)&pkp,  g_kp);
    cudaGetSymbolAddress((void**)&ps,   g_s);
    cudaGetSymbolAddress((void**)&ppp,  g_pp);
    cudaGetSymbolAddress((void**)&pvtp, g_vtp);

    cudaFuncSetAttribute(gemm_i8, cudaFuncAttributeMaxDynamicSharedMemorySize,
                         GEMM_SMEM);

    const ll wStride = (ll)HH * 4 * DD;

    // Δ scales (all powers of 2):  S_proj = Δx*Δw = 2^-31,
    // S_scores = Δq*Δk = 2^-26,  S_ctx = Δp*Δv = 2^-26.
    const float S31 = 4.656612873077393e-10f;   // 2^-31
    const float S26 = 1.4901161193847656e-8f;   // 2^-26

    // 1. pack weights then inputs (ordering chosen so ncu -s lands on a GEMM)
    packBT<<<dim3(HH / 32, DD / 32, 1), dim3(32, 8)>>>(Wq, pwp + 0 * wStride, DD, HH, 0, 0,
                                                       2048.0f, 4.8828125e-4f, 524288.0f);
    packBT<<<dim3(HH / 32, DD / 32, 1), dim3(32, 8)>>>(Wk, pwp + 1 * wStride, DD, HH, 0, 0,
                                                       2048.0f, 4.8828125e-4f, 524288.0f);
    packBT<<<dim3(HH / 32, DD / 32, 1), dim3(32, 8)>>>(Wv, pwp + 2 * wStride, DD, HH, 0, 0,
                                                       2048.0f, 4.8828125e-4f, 524288.0f);
    packA2<<<dim3(DD / 256, MT, 2), 256>>>(x, y, pxp, pyp, DD);

    // 2. projections (fused int-pack epilogues, pack R=4)
    dim3 gProj(HH / 128, MT / 128, 1);
    gemm_i8<<<gProj, 256, GEMM_SMEM>>>(pxp, 0, pwp + 0 * wStride, 0,
                                       pq, pqp, 0, bq, nullptr, HH, DD, 1,
                                       S31, 32.0f, 0.03125f, 8192.0f);
    gemm_i8<<<gProj, 256, GEMM_SMEM>>>(pxp, 0, pwp + 1 * wStride, 0,
                                       nullptr, pkp, 0, bk, nullptr, HH, DD, 2,
                                       S31, 32.0f, 0.03125f, 8192.0f);
    gemm_i8<<<gProj, 256, GEMM_SMEM>>>(pyp, 0, pwp + 2 * wStride, 0,
                                       pv, nullptr, 0, bv, pq, HH, DD, 0,
                                       S31, 0.f, 0.f, 0.f);

    // 3. scores = Q K^T (batched)
    dim3 gScore(SS / 128, SS / 128, BB);
    gemm_i8<<<gScore, 256, GEMM_SMEM>>>(pqp, (ll)SS * 4 * HH, pkp, (ll)SS * 4 * HH,
                                        ps, nullptr, (ll)SS * SS, nullptr, nullptr,
                                        SS, HH, 0, S26, 0.f, 0.f, 0.f);

    // 4. softmax + A-side int pack (R=2)
    softmax_pack<<<MT, 256>>>(ps, ppp);

    // 5. V'^T B-side int pack (R=8)
    packBT<<<dim3(HH / 32, SS / 32, BB), dim3(32, 8)>>>(pv, pvtp, SS, HH,
                                                        (ll)SS * HH, (ll)HH * 4 * SS,
                                                        16.0f, 0.0625f, 4096.0f);

    // 6. context = P V'
    dim3 gCtx(HH / 128, SS / 128, BB);
    gemm_i8<<<gCtx, 256, GEMM_SMEM>>>(ppp, (ll)SS * 4 * SS, pvtp, (ll)HH * 4 * SS,
                                      out, nullptr, (ll)SS * HH, nullptr, nullptr,
                                      HH, SS, 0, S26, 0.f, 0.f, 0.f);
}

// round 13
// speedup vs baseline: 4.0245x; 4.0245x over previous
#include <cuda_runtime.h>
#include <cuda_bf16.h>
#include <cuda_fp16.h>
#include <cstdint>

// Problem constants
#define BB 8
#define SS 2048
#define DD 768
#define HH 768
#define MT (BB*SS)        // 16384
#define K3D (3*DD)        // 2304
#define K2D (2*DD)        // 1536

typedef long long ll;

// ---------------------------------------------------------------------------
// Scratch (device globals — allocation-free rule)
// ---------------------------------------------------------------------------
__device__ __align__(16) __nv_bfloat16 g_xcat[(ll)MT * K3D];   // x  (hi,lo,hi)
__device__ __align__(16) __half        g_yp  [(ll)MT * K2D];   // y  [yh | yl]
__device__ __align__(16) __nv_bfloat16 g_wt[2][(ll)HH * K3D];  // Wq,Wk^T (hi,hi,lo)
__device__ __align__(16) __half        g_wv  [(ll)HH * K2D];   // Wv^T [Wh | Wh]
__device__ __align__(16) float         g_q   [(ll)MT * HH];    // fp32 q (gate)
__device__ __align__(16) __nv_bfloat16 g_qcat[(ll)MT * K3D];   // q (hi,lo,hi)
__device__ __align__(16) __nv_bfloat16 g_kcat[(ll)MT * K3D];   // k (hi,hi,lo)
__device__ __align__(16) __half        g_vh  [(ll)MT * HH];    // v' fp16 row-major
__device__ __align__(16) __half        g_vt  [(ll)BB * HH * SS]; // v'^T fp16
__device__ __align__(16) float         g_s   [(ll)BB * SS * SS]; // scores
__device__ __align__(16) __half        g_ph  [(ll)MT * SS];    // probs fp16

// ---------------------------------------------------------------------------
// PTX helpers
// ---------------------------------------------------------------------------
__device__ __forceinline__ uint32_t s2u(const void* p) {
    return (uint32_t)__cvta_generic_to_shared(p);
}
__device__ __forceinline__ void ldmx4(uint32_t* r, uint32_t a) {
    asm volatile("ldmatrix.sync.aligned.m8n8.x4.shared.b16 {%0,%1,%2,%3}, [%4];"
                 : "=r"(r[0]), "=r"(r[1]), "=r"(r[2]), "=r"(r[3]) : "r"(a));
}
__device__ __forceinline__ void mmabf(float* c, const uint32_t* a, const uint32_t* b) {
    asm volatile("mma.sync.aligned.m16n8k16.row.col.f32.bf16.bf16.f32 "
                 "{%0,%1,%2,%3}, {%4,%5,%6,%7}, {%8,%9}, {%0,%1,%2,%3};"
                 : "+f"(c[0]), "+f"(c[1]), "+f"(c[2]), "+f"(c[3])
                 : "r"(a[0]), "r"(a[1]), "r"(a[2]), "r"(a[3]), "r"(b[0]), "r"(b[1]));
}
__device__ __forceinline__ void mmaf16(float* c, const uint32_t* a, const uint32_t* b) {
    asm volatile("mma.sync.aligned.m16n8k16.row.col.f32.f16.f16.f32 "
                 "{%0,%1,%2,%3}, {%4,%5,%6,%7}, {%8,%9}, {%0,%1,%2,%3};"
                 : "+f"(c[0]), "+f"(c[1]), "+f"(c[2]), "+f"(c[3])
                 : "r"(a[0]), "r"(a[1]), "r"(a[2]), "r"(a[3]), "r"(b[0]), "r"(b[1]));
}
__device__ __forceinline__ void cp16(uint32_t dst, const void* src) {
    asm volatile("cp.async.cg.shared.global [%0], [%1], 16;"
                 :: "r"(dst), "l"(src) : "memory");
}
__device__ __forceinline__ void cp_commit() {
    asm volatile("cp.async.commit_group;" ::: "memory");
}

// ---------------------------------------------------------------------------
// NT GEMM template (bf16 or fp16 mma), cp.async 4-stage ring.
//   C[z][m][n] = sum_k A[z][m][k]*B[z][n][k] (+bias[n]) (*mul)
// Block tile 128x128x32, 8 warps (2x4), warp tile 64x32.
// Outputs (any subset): Cf fp32, Ccat bf16x3 concat (catLo 1=A-side 2=B-side),
//                       Ch fp16.
// ---------------------------------------------------------------------------
#define KPAD 40
#define MAT_BYTES (128 * KPAD * 2)     // 10240
#define STG_BYTES (2 * MAT_BYTES)      // 20480
#define NSTAGE 4
#define GEMM_SMEM (NSTAGE * STG_BYTES) // 81920

__device__ __forceinline__ void issue_stage(const uint16_t* Ag, const uint16_t* Bg,
                                            int K, int kt, uint32_t sA,
                                            int lr, int lc)
{
    const ll k0 = (ll)kt * 32;
    const uint32_t sB = sA + MAT_BYTES;
    cp16(sA + lr * (KPAD * 2) + lc * 2,        Ag + (ll)lr * K + k0 + lc);
    cp16(sA + (lr + 64) * (KPAD * 2) + lc * 2, Ag + (ll)(lr + 64) * K + k0 + lc);
    cp16(sB + lr * (KPAD * 2) + lc * 2,        Bg + (ll)lr * K + k0 + lc);
    cp16(sB + (lr + 64) * (KPAD * 2) + lc * 2, Bg + (ll)(lr + 64) * K + k0 + lc);
    cp_commit();
}

template<int FP16>
__global__ __launch_bounds__(256, 2)
void gemm_nt(const uint16_t* __restrict__ A, ll sAz,
             const uint16_t* __restrict__ B, ll sBz,
             float* __restrict__ Cf, __nv_bfloat16* __restrict__ Ccat,
             __half* __restrict__ Ch, ll sCz,
             const float* __restrict__ bias,
             const float* __restrict__ mul,
             int N, int K, int catLo)
{
    extern __shared__ char dyn[];
    const uint32_t sbase = s2u(dyn);

    const int tid = threadIdx.x;
    const int bx = blockIdx.x, by = blockIdx.y, z = blockIdx.z;
    const int lane = tid & 31, wid = tid >> 5;
    const int wm = (wid >> 2) * 64;
    const int wn = (wid & 3) * 32;

    const uint16_t* Ag = A + (ll)z * sAz + (ll)by * 128 * K;
    const uint16_t* Bg = B + (ll)z * sBz + (ll)bx * 128 * K;

    const int lr = tid >> 2;
    const int lc = (tid & 3) * 8;

    float acc[4][4][4];
    #pragma unroll
    for (int i = 0; i < 4; i++)
        #pragma unroll
        for (int j = 0; j < 4; j++)
            #pragma unroll
            for (int q = 0; q < 4; q++)
                acc[i][j][q] = 0.0f;

    const int aoff = (wm + (lane & 15)) * KPAD + ((lane >> 4) * 8);
    const int bg4 = lane >> 3;
    const int boff = (wn + ((bg4 >> 1) * 8) + (lane & 7)) * KPAD + (bg4 & 1) * 8;

    const int nk = K / 32;

    issue_stage(Ag, Bg, K, 0, sbase + 0 * STG_BYTES, lr, lc);
    issue_stage(Ag, Bg, K, 1, sbase + 1 * STG_BYTES, lr, lc);
    issue_stage(Ag, Bg, K, 2, sbase + 2 * STG_BYTES, lr, lc);

    for (int kt = 0; kt < nk; kt++) {
        asm volatile("cp.async.wait_group %0;" :: "n"(2) : "memory");
        __syncthreads();
        if (kt + 3 < nk)
            issue_stage(Ag, Bg, K, kt + 3, sbase + ((kt + 3) & 3) * STG_BYTES, lr, lc);

        const uint32_t abase = sbase + (kt & 3) * STG_BYTES;
        const uint32_t bbase = abase + MAT_BYTES;
        #pragma unroll
        for (int ks = 0; ks < 2; ks++) {
            uint32_t af[4][4], bfr[2][4];
            #pragma unroll
            for (int mi = 0; mi < 4; mi++)
                ldmx4(af[mi], abase + 2 * (aoff + mi * 16 * KPAD + ks * 16));
            #pragma unroll
            for (int bj = 0; bj < 2; bj++)
                ldmx4(bfr[bj], bbase + 2 * (boff + bj * 16 * KPAD + ks * 16));
            #pragma unroll
            for (int mi = 0; mi < 4; mi++)
                #pragma unroll
                for (int ni = 0; ni < 4; ni++) {
                    if (FP16) mmaf16(acc[mi][ni], af[mi], &bfr[ni >> 1][(ni & 1) * 2]);
                    else      mmabf (acc[mi][ni], af[mi], &bfr[ni >> 1][(ni & 1) * 2]);
                }
        }
    }

    // --- epilogue ---
    const int gq = lane >> 2, tig = lane & 3;
    float* Cz = Cf ? (Cf + (ll)z * sCz) : nullptr;
    __half* Hz = Ch ? (Ch + (ll)z * sCz) : nullptr;
    const float* Mz = mul ? (mul + (ll)z * sCz) : nullptr;

    #pragma unroll
    for (int mi = 0; mi < 4; mi++) {
        #pragma unroll
        for (int ni = 0; ni < 4; ni++) {
            const int row = by * 128 + wm + mi * 16 + gq;
            const int col = bx * 128 + wn + ni * 8 + tig * 2;
            float v0 = acc[mi][ni][0], v1 = acc[mi][ni][1];
            float v2 = acc[mi][ni][2], v3 = acc[mi][ni][3];
            if (bias) {
                float b0 = bias[col], b1 = bias[col + 1];
                v0 += b0; v1 += b1; v2 += b0; v3 += b1;
            }
            const ll o0 = (ll)row * N + col;
            const ll o1 = o0 + 8LL * N;
            if (Mz) {
                v0 *= Mz[o0]; v1 *= Mz[o0 + 1];
                v2 *= Mz[o1]; v3 *= Mz[o1 + 1];
            }
            if (Cz) {
                float2 r01; r01.x = v0; r01.y = v1;
                float2 r23; r23.x = v2; r23.y = v3;
                *reinterpret_cast<float2*>(Cz + o0) = r01;
                *reinterpret_cast<float2*>(Cz + o1) = r23;
            }
            if (Hz) {
                __half2 h01; h01.x = __float2half_rn(v0); h01.y = __float2half_rn(v1);
                __half2 h23; h23.x = __float2half_rn(v2); h23.y = __float2half_rn(v3);
                *reinterpret_cast<__half2*>(Hz + o0) = h01;
                *reinterpret_cast<__half2*>(Hz + o1) = h23;
            }
            if (Ccat) {
                __nv_bfloat16* K0 = Ccat + (ll)row * (3LL * N) + col;
                __nv_bfloat16* K1 = Ccat + (ll)(row + 8) * (3LL * N) + col;
                __nv_bfloat16 h0 = __float2bfloat16(v0);
                __nv_bfloat16 h1 = __float2bfloat16(v1);
                __nv_bfloat16 h2 = __float2bfloat16(v2);
                __nv_bfloat16 h3 = __float2bfloat16(v3);
                __nv_bfloat16 l0 = __float2bfloat16(v0 - __bfloat162float(h0));
                __nv_bfloat16 l1 = __float2bfloat16(v1 - __bfloat162float(h1));
                __nv_bfloat16 l2 = __float2bfloat16(v2 - __bfloat162float(h2));
                __nv_bfloat16 l3 = __float2bfloat16(v3 - __bfloat162float(h3));
                __nv_bfloat162 hp0; hp0.x = h0; hp0.y = h1;
                __nv_bfloat162 hp1; hp1.x = h2; hp1.y = h3;
                __nv_bfloat162 lp0; lp0.x = l0; lp0.y = l1;
                __nv_bfloat162 lp1; lp1.x = l2; lp1.y = l3;
                *reinterpret_cast<__nv_bfloat162*>(K0) = hp0;
                *reinterpret_cast<__nv_bfloat162*>(K1) = hp1;
                *reinterpret_cast<__nv_bfloat162*>(K0 + N) = (catLo == 1) ? lp0 : hp0;
                *reinterpret_cast<__nv_bfloat162*>(K1 + N) = (catLo == 1) ? lp1 : hp1;
                *reinterpret_cast<__nv_bfloat162*>(K0 + 2 * N) = (catLo == 1) ? hp0 : lp0;
                *reinterpret_cast<__nv_bfloat162*>(K1 + 2 * N) = (catLo == 1) ? hp1 : lp1;
            }
        }
    }
}

// ---------------------------------------------------------------------------
// fp32 -> bf16x3 split (A-side: hi,lo,hi), src [R,C] -> dst [R,3C]
// ---------------------------------------------------------------------------
__global__ void cat_split(const float* __restrict__ src, __nv_bfloat16* __restrict__ dst,
                          int C)
{
    const ll r = blockIdx.y;
    const int c = blockIdx.x * 256 + threadIdx.x;
    float x = src[r * C + c];
    __nv_bfloat16 hi = __float2bfloat16(x);
    __nv_bfloat16 lo = __float2bfloat16(x - __bfloat162float(hi));
    __nv_bfloat16* d = dst + r * (3LL * C);
    d[c] = hi;
    d[C + c] = lo;
    d[2LL * C + c] = hi;
}

// ---------------------------------------------------------------------------
// Transposed bf16x3 split (B-side: hi,hi,lo): src [P,Q] fp32 -> dst [Q,3P]
// ---------------------------------------------------------------------------
__global__ void cat_split_t(const float* __restrict__ src, __nv_bfloat16* __restrict__ dst,
                            int P, int Q)
{
    __shared__ float t[32][33];
    const int c0 = blockIdx.x * 32, r0 = blockIdx.y * 32;
    const int tx = threadIdx.x, ty = threadIdx.y;

    #pragma unroll
    for (int i = 0; i < 4; i++)
        t[ty + 8 * i][tx] = src[(ll)(r0 + ty + 8 * i) * Q + c0 + tx];
    __syncthreads();
    #pragma unroll
    for (int i = 0; i < 4; i++) {
        float x = t[tx][ty + 8 * i];
        __nv_bfloat16 hi = __float2bfloat16(x);
        __nv_bfloat16 lo = __float2bfloat16(x - __bfloat162float(hi));
        __nv_bfloat16* dr = dst + (ll)(c0 + ty + 8 * i) * (3LL * P);
        dr[r0 + tx] = hi;
        dr[P + r0 + tx] = hi;
        dr[2LL * P + r0 + tx] = lo;
    }
}

// ---------------------------------------------------------------------------
// y fp32 [R,C] -> fp16 pair [R,2C]: [yh | yl]
// ---------------------------------------------------------------------------
__global__ void pack_y(const float* __restrict__ src, __half* __restrict__ dst, int C)
{
    const ll r = blockIdx.y;
    const int c = blockIdx.x * 256 + threadIdx.x;
    float a = src[r * C + c];
    __half h = __float2half_rn(a);
    __half l = __float2half_rn(a - __half2float(h));
    __half* d = dst + r * (2LL * C);
    d[c] = h;
    d[C + c] = l;
}

// ---------------------------------------------------------------------------
// Wv fp32 [P,Q] -> Wv^T fp16 [Q,2P]: [Wh | Wh]
// ---------------------------------------------------------------------------
__global__ void pack_wv(const float* __restrict__ src, __half* __restrict__ dst,
                        int P, int Q)
{
    __shared__ float t[32][33];
    const int c0 = blockIdx.x * 32, r0 = blockIdx.y * 32;
    const int tx = threadIdx.x, ty = threadIdx.y;

    #pragma unroll
    for (int i = 0; i < 4; i++)
        t[ty + 8 * i][tx] = src[(ll)(r0 + ty + 8 * i) * Q + c0 + tx];
    __syncthreads();
    #pragma unroll
    for (int i = 0; i < 4; i++) {
        __half h = __float2half_rn(t[tx][ty + 8 * i]);
        __half* dr = dst + (ll)(c0 + ty + 8 * i) * (2LL * P);
        dr[r0 + tx] = h;
        dr[P + r0 + tx] = h;
    }
}

// ---------------------------------------------------------------------------
// fp16 transpose: vh [z*SS + s][h] -> vt [z][h][s]
// ---------------------------------------------------------------------------
__global__ void transpose_h(const __half* __restrict__ src, __half* __restrict__ dst)
{
    __shared__ __half t[32][33];
    const int z = blockIdx.z;
    const int h0 = blockIdx.x * 32, s0 = blockIdx.y * 32;
    const int tx = threadIdx.x, ty = threadIdx.y;
    const __half* s = src + (ll)z * SS * HH;
    __half* d = dst + (ll)z * HH * SS;

    #pragma unroll
    for (int i = 0; i < 4; i++)
        t[ty + 8 * i][tx] = s[(ll)(s0 + ty + 8 * i) * HH + h0 + tx];
    __syncthreads();
    #pragma unroll
    for (int i = 0; i < 4; i++)
        d[(ll)(h0 + ty + 8 * i) * SS + s0 + tx] = t[tx][ty + 8 * i];
}

// ---------------------------------------------------------------------------
// Softmax + fp16 store: scores row fp32 -> probs row fp16
// ---------------------------------------------------------------------------
__global__ void softmax_h(const float* __restrict__ S, __half* __restrict__ P)
{
    const ll row = blockIdx.x;
    const float* p = S + row * (ll)SS;
    __half* d = P + row * (ll)SS;
    const int t = threadIdx.x;
    __shared__ float red[32];

    float v[8];
    float m = -1e30f;
    #pragma unroll
    for (int i = 0; i < 8; i++) {
        v[i] = p[t + i * 256];
        m = fmaxf(m, v[i]);
    }
    #pragma unroll
    for (int o = 16; o > 0; o >>= 1) m = fmaxf(m, __shfl_xor_sync(0xffffffffu, m, o));
    if ((t & 31) == 0) red[t >> 5] = m;
    __syncthreads();
    if (t < 32) {
        float mm = (t < 8) ? red[t] : -1e30f;
        #pragma unroll
        for (int o = 16; o > 0; o >>= 1) mm = fmaxf(mm, __shfl_xor_sync(0xffffffffu, mm, o));
        if (t == 0) red[0] = mm;
    }
    __syncthreads();
    m = red[0];
    __syncthreads();

    float sum = 0.0f;
    #pragma unroll
    for (int i = 0; i < 8; i++) {
        v[i] = __expf(v[i] - m);
        sum += v[i];
    }
    #pragma unroll
    for (int o = 16; o > 0; o >>= 1) sum += __shfl_xor_sync(0xffffffffu, sum, o);
    if ((t & 31) == 0) red[t >> 5] = sum;
    __syncthreads();
    if (t < 32) {
        float ss = (t < 8) ? red[t] : 0.0f;
        #pragma unroll
        for (int o = 16; o > 0; o >>= 1) ss += __shfl_xor_sync(0xffffffffu, ss, o);
        if (t == 0) red[0] = ss;
    }
    __syncthreads();
    const float inv = 1.0f / red[0];

    #pragma unroll
    for (int i = 0; i < 8; i++)
        d[t + i * 256] = __float2half_rn(v[i] * inv);
}

// ---------------------------------------------------------------------------
extern "C" void kernel_launch(void* const* d_in, const int* in_sizes, int n_in,
                              void* d_out, int out_size)
{
    const float* x  = (const float*)d_in[0];
    const float* y  = (const float*)d_in[1];
    const float* Wq = (const float*)d_in[2];
    const float* bq = (const float*)d_in[3];
    const float* Wk = (const float*)d_in[4];
    const float* bk = (const float*)d_in[5];
    const float* Wv = (const float*)d_in[6];
    const float* bv = (const float*)d_in[7];
    float* out = (float*)d_out;

    __nv_bfloat16 *pxcat, *pwt, *pqcat, *pkcat;
    __half *pyp, *pwv, *pvh, *pvt, *pph;
    float *pq, *ps;
    cudaGetSymbolAddress((void**)&pxcat, g_xcat);
    cudaGetSymbolAddress((void**)&pyp,   g_yp);
    cudaGetSymbolAddress((void**)&pwt,   g_wt);
    cudaGetSymbolAddress((void**)&pwv,   g_wv);
    cudaGetSymbolAddress((void**)&pq,    g_q);
    cudaGetSymbolAddress((void**)&pqcat, g_qcat);
    cudaGetSymbolAddress((void**)&pkcat, g_kcat);
    cudaGetSymbolAddress((void**)&pvh,   g_vh);
    cudaGetSymbolAddress((void**)&pvt,   g_vt);
    cudaGetSymbolAddress((void**)&ps,    g_s);
    cudaGetSymbolAddress((void**)&pph,   g_ph);

    cudaFuncSetAttribute(gemm_nt<0>, cudaFuncAttributeMaxDynamicSharedMemorySize,
                         GEMM_SMEM);
    cudaFuncSetAttribute(gemm_nt<1>, cudaFuncAttributeMaxDynamicSharedMemorySize,
                         GEMM_SMEM);

    const ll wtStride = (ll)HH * K3D;

    // 1-5. pack inputs + weights (5 launches; ncu -s 5 lands on the Q GEMM)
    cat_split<<<dim3(DD / 256, MT), 256>>>(x, pxcat, DD);
    pack_y<<<dim3(DD / 256, MT), 256>>>(y, pyp, DD);
    cat_split_t<<<dim3(HH / 32, DD / 32), dim3(32, 8)>>>(Wq, pwt + 0 * wtStride, DD, HH);
    cat_split_t<<<dim3(HH / 32, DD / 32), dim3(32, 8)>>>(Wk, pwt + 1 * wtStride, DD, HH);
    pack_wv<<<dim3(HH / 32, DD / 32), dim3(32, 8)>>>(Wv, pwv, DD, HH);

    // 6. Q proj (bf16x3): fp32 q (gating) + qcat (hi,lo,hi)
    dim3 gProj(HH / 128, MT / 128, 1);
    gemm_nt<0><<<gProj, 256, GEMM_SMEM>>>((const uint16_t*)pxcat, 0,
                                          (const uint16_t*)(pwt + 0 * wtStride), 0,
                                          pq, pqcat, nullptr, 0, bq, nullptr, HH, K3D, 1);
    // 7. K proj (bf16x3): kcat (hi,hi,lo)
    gemm_nt<0><<<gProj, 256, GEMM_SMEM>>>((const uint16_t*)pxcat, 0,
                                          (const uint16_t*)(pwt + 1 * wtStride), 0,
                                          nullptr, pkcat, nullptr, 0, bk, nullptr, HH, K3D, 2);
    // 8. V proj (fp16 2-product, K=1536): v' = (yWv+bv) ⊙ q -> fp16
    gemm_nt<1><<<gProj, 256, GEMM_SMEM>>>((const uint16_t*)pyp, 0,
                                          (const uint16_t*)pwv, 0,
                                          nullptr, nullptr, pvh, 0, bv, pq, HH, K2D, 0);

    // 9. scores = Q K^T (bf16x3, batched)
    dim3 gScore(SS / 128, SS / 128, BB);
    gemm_nt<0><<<gScore, 256, GEMM_SMEM>>>((const uint16_t*)pqcat, (ll)SS * K3D,
                                           (const uint16_t*)pkcat, (ll)SS * K3D,
                                           ps, nullptr, nullptr, (ll)SS * SS,
                                           nullptr, nullptr, SS, K3D, 0);

    // 10. softmax -> fp16 probs
    softmax_h<<<MT, 256>>>(ps, pph);

    // 11. v'^T (fp16 transpose per batch)
    transpose_h<<<dim3(HH / 32, SS / 32, BB), dim3(32, 8)>>>(pvh, pvt);

    // 12. context = P V' (plain fp16, K=2048)
    dim3 gCtx(HH / 128, SS / 128, BB);
    gemm_nt<1><<<gCtx, 256, GEMM_SMEM>>>((const uint16_t*)pph, (ll)SS * SS,
                                         (const uint16_t*)pvt, (ll)HH * SS,
                                         out, nullptr, nullptr, (ll)SS * HH,
                                         nullptr, nullptr, HH, SS, 0);
}